// round 14
// baseline (speedup 1.0000x reference)
#include <cuda_runtime.h>
#include <math.h>

// Problem constants
#define BN    16
#define Hn    256
#define Wn    256
#define IMG   (Hn * Wn)          // 65536
#define NTOT  (BN * IMG)         // 1048576
#define SEG   8                  // rows per fused band
#define NB    (Hn / SEG)         // 32 bands per image
#define NWORD 8                  // 256 rows / 32 bits
#define NPART (BN * NB)          // 512 fused CTAs / partials
#define SENT_LO (-1000000)
#define SENT_HI ( 1000000)

// Scratch (device globals — no allocation allowed)
// Layout: g_bits[(b*Wn + col)*8 + w] -> 8 words of one column contiguous (32B)
__device__ unsigned g_bits[BN * Wn * NWORD];
__device__ float    g_part[NPART * 8];   // pt, p, t, bce, phi*p, max|phi|

__device__ __forceinline__ float sqrt_approx(float x) {
    float r;
    asm("sqrt.approx.f32 %0, %1;" : "=f"(r) : "f"(x));
    return r;
}
__device__ __forceinline__ float rcp_approx(float x) {
    float r;
    asm("rcp.approx.f32 %0, %1;" : "=f"(r) : "f"(x));
    return r;
}

// ---------------------------------------------------------------------------
// Bits kernel: per-column occupancy bitmask via ballot transpose.
// One CTA = 32 rows x 64 cols. grid: (BN, 8 words, 4 col-quarters), block 256.
// ---------------------------------------------------------------------------
__global__ __launch_bounds__(256) void bits_kernel(const float* __restrict__ tgt) {
    __shared__ float tile[32][65];
    int b = blockIdx.x;
    int w = blockIdx.y;
    int q = blockIdx.z;
    int tid  = threadIdx.x;
    int lane = tid & 31;
    int wp   = tid >> 5;

    const float* src = tgt + b * IMG + (w * 32) * Wn + q * 64;
    #pragma unroll
    for (int k = 0; k < 2; k++) {
        int idx = tid + k * 256;
        int r = idx >> 4;
        int c = (idx & 15) * 4;
        float4 v = *(const float4*)(src + r * Wn + c);
        tile[r][c + 0] = v.x;
        tile[r][c + 1] = v.y;
        tile[r][c + 2] = v.z;
        tile[r][c + 3] = v.w;
    }
    __syncthreads();

    #pragma unroll
    for (int cc = 0; cc < 8; cc++) {
        int c = wp * 8 + cc;
        unsigned word = __ballot_sync(0xFFFFFFFFu, tile[lane][c] != 0.0f);
        if (lane == cc)
            g_bits[(b * Wn + q * 64 + c) * NWORD + w] = word;
    }
}

// ---------------------------------------------------------------------------
// Bit-scan helpers over an 8-word (256-bit) column, absolute bit positions.
// ---------------------------------------------------------------------------
__device__ __forceinline__ int hi_below(const unsigned* Z, int base) {
    int w = base >> 5;
    int off = base & 31;
    unsigned cur = off ? (Z[w] & ((1u << off) - 1u)) : 0u;
    while (true) {
        if (cur) return w * 32 + 31 - __clz(cur);
        if (--w < 0) return SENT_LO;
        cur = Z[w];
    }
}
__device__ __forceinline__ int lo_from(const unsigned* Z, int start) {
    int w = start >> 5;
    if (w >= NWORD) return SENT_HI;
    unsigned cur = Z[w] & (0xFFFFFFFFu << (start & 31));
    while (true) {
        if (cur) return w * 32 + __ffs(cur) - 1;
        if (++w >= NWORD) return SENT_HI;
        cur = Z[w];
    }
}

// ---------------------------------------------------------------------------
// Fused kernel: one CTA = one (image, 8-row band). R13 structure plus:
//   - pred values prefetched into registers BEFORE the barrier (their L2/DRAM
//     latency overlaps the vertical pass + rad loop)
//   - sum(t) via popc of the in-band bits (exact for binary masks)
//   - select-form dice/BCE terms (no x*t FMA, no p*t FMUL)
// grid: (BN, 32), block: 256
// ---------------------------------------------------------------------------
__global__ __launch_bounds__(256) void fused_kernel(const float* __restrict__ pred) {
    __shared__ int   s_d[SEG][Wn];        // signed d1^2
    __shared__ float s_red[8][6];

    int b = blockIdx.x;
    int s = blockIdx.y;
    int j = threadIdx.x;
    int base = s * SEG;

    // Prefetch pred early: independent of everything below, MLP=8.
    const float* pr = pred + b * IMG + base * Wn;
    float xv[SEG];
    #pragma unroll
    for (int r = 0; r < SEG; r++) xv[r] = pr[r * Wn + j];

    // Load this column's 256-bit mask: 2 coalesced LDG.128.
    const uint4* gb = (const uint4*)g_bits + (b * Wn + j) * 2;
    uint4 wlo = gb[0];
    uint4 whi = gb[1];
    unsigned Wb[NWORD] = {wlo.x, wlo.y, wlo.z, wlo.w, whi.x, whi.y, whi.z, whi.w};

    unsigned Zin[NWORD];
    #pragma unroll
    for (int w = 0; w < NWORD; w++) Zin[w] = ~Wb[w];

    // Nearest zeros strictly outside the band.
    int lzi = hi_below(Zin, base);
    int lzo = hi_below(Wb,  base);
    int nzi = lo_from(Zin, base + SEG);
    int nzo = lo_from(Wb,  base + SEG);

    unsigned bb = (Wb[base >> 5] >> (base & 31)) & 0xFFu;  // 8 in-band bits

    int ddi[SEG], ddo[SEG];
    #pragma unroll
    for (int r = 0; r < SEG; r++) {
        int i = base + r;
        if ((bb >> r) & 1) lzo = i; else lzi = i;
        ddi[r] = i - lzi;
        ddo[r] = i - lzo;
    }
    int bestv[SEG];
    #pragma unroll
    for (int r = SEG - 1; r >= 0; r--) {
        int i = base + r;
        int mj = (bb >> r) & 1;
        if (mj) nzo = i; else nzi = i;
        int di = min(min(ddi[r], nzi - i), 512);
        int dq = min(min(ddo[r], nzo - i), 512);
        int d2i = di * di;
        int d2q = dq * dq;
        s_d[r][j] = mj ? d2i : -d2q;      // signed for neighbors
        bestv[r]  = mj ? d2i : d2q;       // own value in registers
    }
    __syncthreads();

    // Guarded horizontal pass: per-row guard + per-thread early exit (exact).
    int lim = 0;
    #pragma unroll
    for (int r = 0; r < SEG; r++) lim = max(lim, bestv[r]);

    for (int rad = 1; rad * rad < lim; rad++) {
        int off = rad * rad;
        int kl = j - rad;
        int kr = j + rad;
        bool okl = (kl >= 0);
        bool okr = (kr < Wn);
        #pragma unroll
        for (int r = 0; r < SEG; r++) {
            if (off < bestv[r]) {
                bool pos = ((bb >> r) & 1);
                if (okl) {
                    int vv = s_d[r][kl];
                    int v  = pos ? vv : -vv;
                    bestv[r] = min(bestv[r], max(v, 0) + off);
                }
                if (okr) {
                    int vv = s_d[r][kr];
                    int v  = pos ? vv : -vv;
                    bestv[r] = min(bestv[r], max(v, 0) + off);
                }
            }
        }
        lim = 0;
        #pragma unroll
        for (int r = 0; r < SEG; r++) lim = max(lim, bestv[r]);
    }

    // Loss terms (single exp chain + approx rcp/sqrt; select forms).
    float v0 = 0.f, v1 = 0.f, v3 = 0.f, v4 = 0.f, vmax = 0.f;
    float v2 = (float)__popc((int)bb);    // sum of t over this thread's pixels
    #pragma unroll
    for (int r = 0; r < SEG; r++) {
        bool pos = ((bb >> r) & 1);
        float dist = sqrt_approx((float)bestv[r]);
        float phi  = pos ? -dist : dist;     // outside - inside

        float x  = xv[r];
        float e  = __expf(-fabsf(x));
        float rc = rcp_approx(1.0f + e);
        float p  = (x >= 0.0f) ? rc : e * rc;
        // t in {0,1}: bce = relu(pos ? -x : x) + log(1+e)
        float bce = fmaxf(pos ? -x : x, 0.0f) + __logf(1.0f + e);

        v0 += pos ? p : 0.0f;
        v1 += p;
        v3 += bce;
        v4 += phi * p;
        vmax = fmaxf(vmax, dist);            // dist == |phi|
    }

    // Deterministic block reduction.
    #pragma unroll
    for (int o = 16; o > 0; o >>= 1) {
        v0 += __shfl_xor_sync(0xFFFFFFFFu, v0, o);
        v1 += __shfl_xor_sync(0xFFFFFFFFu, v1, o);
        v2 += __shfl_xor_sync(0xFFFFFFFFu, v2, o);
        v3 += __shfl_xor_sync(0xFFFFFFFFu, v3, o);
        v4 += __shfl_xor_sync(0xFFFFFFFFu, v4, o);
        vmax = fmaxf(vmax, __shfl_xor_sync(0xFFFFFFFFu, vmax, o));
    }
    int wp = j >> 5;
    if ((j & 31) == 0) {
        s_red[wp][0] = v0; s_red[wp][1] = v1; s_red[wp][2] = v2;
        s_red[wp][3] = v3; s_red[wp][4] = v4; s_red[wp][5] = vmax;
    }
    __syncthreads();
    if (j == 0) {
        float a0 = 0, a1 = 0, a2 = 0, a3 = 0, a4 = 0, am = 0;
        #pragma unroll
        for (int k = 0; k < 8; k++) {
            a0 += s_red[k][0]; a1 += s_red[k][1]; a2 += s_red[k][2];
            a3 += s_red[k][3]; a4 += s_red[k][4]; am = fmaxf(am, s_red[k][5]);
        }
        float* op = g_part + (b * NB + s) * 8;
        op[0] = a0; op[1] = a1; op[2] = a2;
        op[3] = a3; op[4] = a4; op[5] = am;
    }
}

// ---------------------------------------------------------------------------
// Final kernel: 512 partials -> scalar. Warp w handles image w (32 bands).
// grid: 1, block: 512
// ---------------------------------------------------------------------------
__global__ __launch_bounds__(512) void final_kernel(float* __restrict__ out) {
    __shared__ float s_img[BN];
    __shared__ float s_g[16][4];

    int t = threadIdx.x;
    const float* p = g_part + t * 8;
    float v0 = p[0], v1 = p[1], v2 = p[2], v3 = p[3], v4 = p[4], vm = p[5];

    // Per-image reduce (warp w == image w) for the boundary term.
    float st = v2, sp = v4, mx = vm;
    #pragma unroll
    for (int o = 16; o > 0; o >>= 1) {
        st += __shfl_xor_sync(0xFFFFFFFFu, st, o);
        sp += __shfl_xor_sync(0xFFFFFFFFu, sp, o);
        mx = fmaxf(mx, __shfl_xor_sync(0xFFFFFFFFu, mx, o));
    }
    int w = t >> 5;
    if ((t & 31) == 0) {
        s_img[w] = (st > 0.0f) ? sp / (mx + 1e-8f) : 0.0f;
    }

    // Global sums across all 512 threads.
    #pragma unroll
    for (int o = 16; o > 0; o >>= 1) {
        v0 += __shfl_xor_sync(0xFFFFFFFFu, v0, o);
        v1 += __shfl_xor_sync(0xFFFFFFFFu, v1, o);
        v2 += __shfl_xor_sync(0xFFFFFFFFu, v2, o);
        v3 += __shfl_xor_sync(0xFFFFFFFFu, v3, o);
    }
    if ((t & 31) == 0) {
        s_g[w][0] = v0; s_g[w][1] = v1; s_g[w][2] = v2; s_g[w][3] = v3;
    }
    __syncthreads();

    if (t == 0) {
        float inter = 0, sum_p = 0, sum_t = 0, bces = 0;
        #pragma unroll
        for (int k = 0; k < 16; k++) {
            inter += s_g[k][0]; sum_p += s_g[k][1];
            sum_t += s_g[k][2]; bces  += s_g[k][3];
        }
        float bsum = 0;
        #pragma unroll
        for (int k = 0; k < BN; k++) bsum += s_img[k];

        float smooth   = 1e-6f;
        float dice     = 1.0f - (2.0f * inter + smooth) / (sum_p + sum_t + smooth);
        float boundary = bsum / (float)NTOT;
        float bce      = bces / (float)NTOT;
        // alpha = 0.005 -> beta = 0.595, 1-beta = 0.405
        out[0] = 0.405f * dice + 0.595f * boundary + 0.4f * bce;
    }
}

// ---------------------------------------------------------------------------
extern "C" void kernel_launch(void* const* d_in, const int* in_sizes, int n_in,
                              void* d_out, int out_size) {
    const float* pred = (const float*)d_in[0];
    const float* tgt  = (const float*)d_in[1];
    float* out = (float*)d_out;

    bits_kernel<<<dim3(BN, NWORD, 4), 256>>>(tgt);
    fused_kernel<<<dim3(BN, NB), 256>>>(pred);
    final_kernel<<<1, 512>>>(out);
}

// round 15
// speedup vs baseline: 1.0022x; 1.0022x over previous
#include <cuda_runtime.h>
#include <math.h>

// Problem constants
#define BN    16
#define Hn    256
#define Wn    256
#define IMG   (Hn * Wn)          // 65536
#define NTOT  (BN * IMG)         // 1048576
#define SEG   8                  // rows per fused band
#define NB    (Hn / SEG)         // 32 bands per image
#define NWORD 8                  // 256 rows / 32 bits
#define NPART (BN * NB)          // 512 fused CTAs / partials
#define SENT_LO (-1000000)
#define SENT_HI ( 1000000)

// Scratch (device globals — no allocation allowed)
// Layout: g_bits[(b*Wn + col)*8 + w] -> 8 words of one column contiguous (32B)
__device__ unsigned g_bits[BN * Wn * NWORD];
__device__ float    g_part[NPART * 8];   // pt, p, t, bce, phi*p, max|phi|

__device__ __forceinline__ float sqrt_approx(float x) {
    float r;
    asm("sqrt.approx.f32 %0, %1;" : "=f"(r) : "f"(x));
    return r;
}
__device__ __forceinline__ float rcp_approx(float x) {
    float r;
    asm("rcp.approx.f32 %0, %1;" : "=f"(r) : "f"(x));
    return r;
}

// ---------------------------------------------------------------------------
// Bits kernel: per-column occupancy bitmask via ballot transpose.
// One CTA = 32 rows x 64 cols. grid: (BN, 8 words, 4 col-quarters), block 256.
// Triggers programmatic launch completion right after its stores.
// ---------------------------------------------------------------------------
__global__ __launch_bounds__(256) void bits_kernel(const float* __restrict__ tgt) {
    __shared__ float tile[32][65];
    int b = blockIdx.x;
    int w = blockIdx.y;
    int q = blockIdx.z;
    int tid  = threadIdx.x;
    int lane = tid & 31;
    int wp   = tid >> 5;

    const float* src = tgt + b * IMG + (w * 32) * Wn + q * 64;
    #pragma unroll
    for (int k = 0; k < 2; k++) {
        int idx = tid + k * 256;
        int r = idx >> 4;
        int c = (idx & 15) * 4;
        float4 v = *(const float4*)(src + r * Wn + c);
        tile[r][c + 0] = v.x;
        tile[r][c + 1] = v.y;
        tile[r][c + 2] = v.z;
        tile[r][c + 3] = v.w;
    }
    __syncthreads();

    #pragma unroll
    for (int cc = 0; cc < 8; cc++) {
        int c = wp * 8 + cc;
        unsigned word = __ballot_sync(0xFFFFFFFFu, tile[lane][c] != 0.0f);
        if (lane == cc)
            g_bits[(b * Wn + q * 64 + c) * NWORD + w] = word;
    }
    cudaTriggerProgrammaticLaunchCompletion();
}

// ---------------------------------------------------------------------------
// Bit-scan helpers over an 8-word (256-bit) column, absolute bit positions.
// ---------------------------------------------------------------------------
__device__ __forceinline__ int hi_below(const unsigned* Z, int base) {
    int w = base >> 5;
    int off = base & 31;
    unsigned cur = off ? (Z[w] & ((1u << off) - 1u)) : 0u;
    while (true) {
        if (cur) return w * 32 + 31 - __clz(cur);
        if (--w < 0) return SENT_LO;
        cur = Z[w];
    }
}
__device__ __forceinline__ int lo_from(const unsigned* Z, int start) {
    int w = start >> 5;
    if (w >= NWORD) return SENT_HI;
    unsigned cur = Z[w] & (0xFFFFFFFFu << (start & 31));
    while (true) {
        if (cur) return w * 32 + __ffs(cur) - 1;
        if (++w >= NWORD) return SENT_HI;
        cur = Z[w];
    }
}

// ---------------------------------------------------------------------------
// Fused kernel (PDL secondary): prefetches pred BEFORE the grid dependency
// sync (overlapping bits_kernel's execution), then proceeds as R14.
// grid: (BN, 32), block: 256
// ---------------------------------------------------------------------------
__global__ __launch_bounds__(256) void fused_kernel(const float* __restrict__ pred) {
    __shared__ int   s_d[SEG][Wn];        // signed d1^2
    __shared__ float s_red[8][6];

    int b = blockIdx.x;
    int s = blockIdx.y;
    int j = threadIdx.x;
    int base = s * SEG;

    // Prefetch pred: independent of bits_kernel's output.
    const float* pr = pred + b * IMG + base * Wn;
    float xv[SEG];
    #pragma unroll
    for (int r = 0; r < SEG; r++) xv[r] = pr[r * Wn + j];

    // Wait for bits_kernel completion before reading g_bits.
    cudaGridDependencySynchronize();

    // Load this column's 256-bit mask: 2 coalesced LDG.128.
    const uint4* gb = (const uint4*)g_bits + (b * Wn + j) * 2;
    uint4 wlo = gb[0];
    uint4 whi = gb[1];
    unsigned Wb[NWORD] = {wlo.x, wlo.y, wlo.z, wlo.w, whi.x, whi.y, whi.z, whi.w};

    unsigned Zin[NWORD];
    #pragma unroll
    for (int w = 0; w < NWORD; w++) Zin[w] = ~Wb[w];

    // Nearest zeros strictly outside the band.
    int lzi = hi_below(Zin, base);
    int lzo = hi_below(Wb,  base);
    int nzi = lo_from(Zin, base + SEG);
    int nzo = lo_from(Wb,  base + SEG);

    unsigned bb = (Wb[base >> 5] >> (base & 31)) & 0xFFu;  // 8 in-band bits

    int ddi[SEG], ddo[SEG];
    #pragma unroll
    for (int r = 0; r < SEG; r++) {
        int i = base + r;
        if ((bb >> r) & 1) lzo = i; else lzi = i;
        ddi[r] = i - lzi;
        ddo[r] = i - lzo;
    }
    int bestv[SEG];
    #pragma unroll
    for (int r = SEG - 1; r >= 0; r--) {
        int i = base + r;
        int mj = (bb >> r) & 1;
        if (mj) nzo = i; else nzi = i;
        int di = min(min(ddi[r], nzi - i), 512);
        int dq = min(min(ddo[r], nzo - i), 512);
        int d2i = di * di;
        int d2q = dq * dq;
        s_d[r][j] = mj ? d2i : -d2q;      // signed for neighbors
        bestv[r]  = mj ? d2i : d2q;       // own value in registers
    }
    __syncthreads();

    // Guarded horizontal pass: per-row guard + per-thread early exit (exact).
    int lim = 0;
    #pragma unroll
    for (int r = 0; r < SEG; r++) lim = max(lim, bestv[r]);

    for (int rad = 1; rad * rad < lim; rad++) {
        int off = rad * rad;
        int kl = j - rad;
        int kr = j + rad;
        bool okl = (kl >= 0);
        bool okr = (kr < Wn);
        #pragma unroll
        for (int r = 0; r < SEG; r++) {
            if (off < bestv[r]) {
                bool pos = ((bb >> r) & 1);
                if (okl) {
                    int vv = s_d[r][kl];
                    int v  = pos ? vv : -vv;
                    bestv[r] = min(bestv[r], max(v, 0) + off);
                }
                if (okr) {
                    int vv = s_d[r][kr];
                    int v  = pos ? vv : -vv;
                    bestv[r] = min(bestv[r], max(v, 0) + off);
                }
            }
        }
        lim = 0;
        #pragma unroll
        for (int r = 0; r < SEG; r++) lim = max(lim, bestv[r]);
    }

    // Loss terms (single exp chain + approx rcp/sqrt; select forms).
    float v0 = 0.f, v1 = 0.f, v3 = 0.f, v4 = 0.f, vmax = 0.f;
    float v2 = (float)__popc((int)bb);    // sum of t over this thread's pixels
    #pragma unroll
    for (int r = 0; r < SEG; r++) {
        bool pos = ((bb >> r) & 1);
        float dist = sqrt_approx((float)bestv[r]);
        float phi  = pos ? -dist : dist;     // outside - inside

        float x  = xv[r];
        float e  = __expf(-fabsf(x));
        float rc = rcp_approx(1.0f + e);
        float p  = (x >= 0.0f) ? rc : e * rc;
        // t in {0,1}: bce = relu(pos ? -x : x) + log(1+e)
        float bce = fmaxf(pos ? -x : x, 0.0f) + __logf(1.0f + e);

        v0 += pos ? p : 0.0f;
        v1 += p;
        v3 += bce;
        v4 += phi * p;
        vmax = fmaxf(vmax, dist);            // dist == |phi|
    }

    // Deterministic block reduction.
    #pragma unroll
    for (int o = 16; o > 0; o >>= 1) {
        v0 += __shfl_xor_sync(0xFFFFFFFFu, v0, o);
        v1 += __shfl_xor_sync(0xFFFFFFFFu, v1, o);
        v2 += __shfl_xor_sync(0xFFFFFFFFu, v2, o);
        v3 += __shfl_xor_sync(0xFFFFFFFFu, v3, o);
        v4 += __shfl_xor_sync(0xFFFFFFFFu, v4, o);
        vmax = fmaxf(vmax, __shfl_xor_sync(0xFFFFFFFFu, vmax, o));
    }
    int wp = j >> 5;
    if ((j & 31) == 0) {
        s_red[wp][0] = v0; s_red[wp][1] = v1; s_red[wp][2] = v2;
        s_red[wp][3] = v3; s_red[wp][4] = v4; s_red[wp][5] = vmax;
    }
    __syncthreads();
    if (j == 0) {
        float a0 = 0, a1 = 0, a2 = 0, a3 = 0, a4 = 0, am = 0;
        #pragma unroll
        for (int k = 0; k < 8; k++) {
            a0 += s_red[k][0]; a1 += s_red[k][1]; a2 += s_red[k][2];
            a3 += s_red[k][3]; a4 += s_red[k][4]; am = fmaxf(am, s_red[k][5]);
        }
        float* op = g_part + (b * NB + s) * 8;
        op[0] = a0; op[1] = a1; op[2] = a2;
        op[3] = a3; op[4] = a4; op[5] = am;
    }
    cudaTriggerProgrammaticLaunchCompletion();
}

// ---------------------------------------------------------------------------
// Final kernel (PDL secondary): 512 partials -> scalar. grid 1, block 512.
// ---------------------------------------------------------------------------
__global__ __launch_bounds__(512) void final_kernel(float* __restrict__ out) {
    __shared__ float s_img[BN];
    __shared__ float s_g[16][4];

    cudaGridDependencySynchronize();

    int t = threadIdx.x;
    const float* p = g_part + t * 8;
    float v0 = p[0], v1 = p[1], v2 = p[2], v3 = p[3], v4 = p[4], vm = p[5];

    // Per-image reduce (warp w == image w) for the boundary term.
    float st = v2, sp = v4, mx = vm;
    #pragma unroll
    for (int o = 16; o > 0; o >>= 1) {
        st += __shfl_xor_sync(0xFFFFFFFFu, st, o);
        sp += __shfl_xor_sync(0xFFFFFFFFu, sp, o);
        mx = fmaxf(mx, __shfl_xor_sync(0xFFFFFFFFu, mx, o));
    }
    int w = t >> 5;
    if ((t & 31) == 0) {
        s_img[w] = (st > 0.0f) ? sp / (mx + 1e-8f) : 0.0f;
    }

    // Global sums across all 512 threads.
    #pragma unroll
    for (int o = 16; o > 0; o >>= 1) {
        v0 += __shfl_xor_sync(0xFFFFFFFFu, v0, o);
        v1 += __shfl_xor_sync(0xFFFFFFFFu, v1, o);
        v2 += __shfl_xor_sync(0xFFFFFFFFu, v2, o);
        v3 += __shfl_xor_sync(0xFFFFFFFFu, v3, o);
    }
    if ((t & 31) == 0) {
        s_g[w][0] = v0; s_g[w][1] = v1; s_g[w][2] = v2; s_g[w][3] = v3;
    }
    __syncthreads();

    if (t == 0) {
        float inter = 0, sum_p = 0, sum_t = 0, bces = 0;
        #pragma unroll
        for (int k = 0; k < 16; k++) {
            inter += s_g[k][0]; sum_p += s_g[k][1];
            sum_t += s_g[k][2]; bces  += s_g[k][3];
        }
        float bsum = 0;
        #pragma unroll
        for (int k = 0; k < BN; k++) bsum += s_img[k];

        float smooth   = 1e-6f;
        float dice     = 1.0f - (2.0f * inter + smooth) / (sum_p + sum_t + smooth);
        float boundary = bsum / (float)NTOT;
        float bce      = bces / (float)NTOT;
        // alpha = 0.005 -> beta = 0.595, 1-beta = 0.405
        out[0] = 0.405f * dice + 0.595f * boundary + 0.4f * bce;
    }
}

// ---------------------------------------------------------------------------
extern "C" void kernel_launch(void* const* d_in, const int* in_sizes, int n_in,
                              void* d_out, int out_size) {
    const float* pred = (const float*)d_in[0];
    const float* tgt  = (const float*)d_in[1];
    float* out = (float*)d_out;

    // Kernel 1: plain launch.
    bits_kernel<<<dim3(BN, NWORD, 4), 256>>>(tgt);

    // Kernel 2: PDL secondary — may start while bits_kernel runs.
    {
        cudaLaunchConfig_t cfg = {};
        cudaLaunchAttribute attrs[1];
        attrs[0].id = cudaLaunchAttributeProgrammaticStreamSerialization;
        attrs[0].val.programmaticStreamSerializationAllowed = 1;
        cfg.gridDim = dim3(BN, NB, 1);
        cfg.blockDim = dim3(256, 1, 1);
        cfg.attrs = attrs;
        cfg.numAttrs = 1;
        cfg.stream = 0;
        cudaLaunchKernelEx(&cfg, fused_kernel, pred);
    }

    // Kernel 3: PDL secondary — overlaps launch latency with fused's tail.
    {
        cudaLaunchConfig_t cfg = {};
        cudaLaunchAttribute attrs[1];
        attrs[0].id = cudaLaunchAttributeProgrammaticStreamSerialization;
        attrs[0].val.programmaticStreamSerializationAllowed = 1;
        cfg.gridDim = dim3(1, 1, 1);
        cfg.blockDim = dim3(512, 1, 1);
        cfg.attrs = attrs;
        cfg.numAttrs = 1;
        cfg.stream = 0;
        cudaLaunchKernelEx(&cfg, final_kernel, out);
    }
}